// round 8
// baseline (speedup 1.0000x reference)
#include <cuda_runtime.h>

#define BB 8
#define CC 256
#define HH 96
#define WW 96
#define HS 192
#define WS 192
#define OC 32
#define GG 4
#define CG 64   // CC/GG

typedef unsigned long long u64;

// Offset field scratch: [B][G][HS][WS] x float2 (x-offset, y-offset) interleaved
__device__ float g_off[BB * GG * HS * WS * 2];

#define FMA_F32X2(d, a, b) \
    asm("fma.rn.f32x2 %0, %1, %2, %0;" : "+l"(d) : "l"(a), "l"(b))
#define PACK_F32X2(out, lo, hi) \
    asm("mov.b64 %0, {%1, %2};" : "=l"(out) : "f"(lo), "f"(hi))
#define UNPACK_F32X2(lo, hi, in) \
    asm("mov.b64 {%0, %1}, %2;" : "=f"(lo), "=f"(hi) : "l"(in))

// ---------------------------------------------------------------------------
// Kernel 1: 1x1 conv (32 outputs over 256 channels) + tanh + pixel_shuffle(2)
// CHANNEL-SPLIT: 2 threads per pixel (128 channels each) -> 2x resident warps
// for latency hiding. 16-deep LDG prefetch (MLP=16). fma.rn.f32x2 accums.
// Partial sums reduced through smem (transposed, conflict-free).
// ---------------------------------------------------------------------------
__global__ __launch_bounds__(256) void conv_offset_kernel(
    const float* __restrict__ x, const float* __restrict__ w,
    const float* __restrict__ bias)
{
    __shared__ __align__(16) float wT[CC * OC];          // 32 KB: wT[c*32+o]
    __shared__ __align__(16) u64 accbuf[16][128];        // 16 KB, transposed

    int tid  = threadIdx.x;
    int pixl = tid & 127;            // local pixel 0..127
    int half = tid >> 7;             // 0: ch 0-127, 1: ch 128-255

    #pragma unroll
    for (int k = 0; k < (CC * OC) / 256; ++k) {
        int flat = tid + k * 256;
        int c = flat >> 5, o = flat & 31;
        wT[flat] = w[o * CC + c];
    }
    __syncthreads();

    int p   = blockIdx.x * 128 + pixl;      // 0 .. B*H*W-1
    int b   = p / (HH * WW);
    int rem = p - b * (HH * WW);
    int h   = rem / WW;
    int wp  = rem - h * WW;

    u64 acc[OC / 2];
    #pragma unroll
    for (int q = 0; q < OC / 2; ++q) acc[q] = 0ull;

    const float* xp = x + (b * CC + half * 128) * (HH * WW) + h * WW + wp;
    const float* wbase = wT + half * 128 * OC;
    #pragma unroll 1
    for (int c0 = 0; c0 < 128; c0 += 16) {
        float xv[16];
        #pragma unroll
        for (int u = 0; u < 16; ++u)                 // 16 independent LDGs
            xv[u] = __ldg(xp + (c0 + u) * (HH * WW));
        #pragma unroll
        for (int u = 0; u < 16; ++u) {
            u64 xx;
            PACK_F32X2(xx, xv[u], xv[u]);
            const ulonglong2* wrow = (const ulonglong2*)(wbase + (c0 + u) * OC);
            #pragma unroll
            for (int q = 0; q < OC / 4; ++q) {
                ulonglong2 wv = wrow[q];             // broadcast LDS.128
                FMA_F32X2(acc[2 * q + 0], xx, wv.x);
                FMA_F32X2(acc[2 * q + 1], xx, wv.y);
            }
        }
    }

    // half 1 publishes partials; half 0 reduces + finishes
    if (half == 1) {
        #pragma unroll
        for (int q = 0; q < OC / 2; ++q) accbuf[q][pixl] = acc[q];
    }
    __syncthreads();
    if (half == 1) return;

    #pragma unroll
    for (int q = 0; q < OC / 2; ++q) {
        float a0, a1, b0, b1;
        UNPACK_F32X2(a0, a1, acc[q]);
        UNPACK_F32X2(b0, b1, accbuf[q][pixl]);
        a0 += b0 + bias[2 * q];
        a1 += b1 + bias[2 * q + 1];
        #pragma unroll
        for (int s = 0; s < 2; ++s) {
            int o    = 2 * q + s;
            float v  = tanhf(s ? a1 : a0);
            int co   = o >> 2;          // 0..7  channel after shuffle
            int i    = (o >> 1) & 1;    // row sub-position
            int j    = o & 1;           // col sub-position
            int gidx = co >> 1;         // group 0..3
            int k    = co & 1;          // 0 = x-offset, 1 = y-offset
            int hs = 2 * h + i, ws = 2 * wp + j;
            g_off[((((b * GG + gidx) * HS + hs) * WS + ws) << 1) + k] = v;
        }
    }
}

// ---------------------------------------------------------------------------
// Kernel 2: bilinear border grid_sample. One thread = 2 horizontally adjacent
// output pixels -> STG.64 streaming stores, one LDG.128 for both offset
// pairs, 8 independent gather LDGs per channel iteration.
// ---------------------------------------------------------------------------
__global__ __launch_bounds__(256) void gather_kernel(
    const float* __restrict__ x, float* __restrict__ out)
{
    const int tiles = (HS * WS / 2) / 256;  // 72 pair-tiles per (b,g)
    int bg   = blockIdx.x / tiles;          // 0..31 = b*4 + gidx
    int t    = (blockIdx.x - bg * tiles) * 256 + threadIdx.x;
    int hs   = t / (WS / 2);
    int ws0  = (t - hs * (WS / 2)) * 2;     // even column of the pair
    int b    = bg >> 2;
    int gidx = bg & 3;

    // both offset pairs in one LDG.128: (x0,y0,x1,y1)
    float4 oo = __ldg((const float4*)g_off + (((bg * HS + hs) * WS + ws0) >> 1));
    float offx[2] = {oo.x, oo.z};
    float offy[2] = {oo.y, oo.w};

    int   i00[2], dx[2], dy[2];
    float w00[2], w01[2], w10[2], w11[2];
    #pragma unroll
    for (int j = 0; j < 2; ++j) {
        // grid math collapsed: gx = (base_x + 0.125*off + 1)*48 - 0.5
        float gx = (float)(ws0 + j) * 0.5f - 0.25f + 6.0f * offx[j];
        float gy = (float)hs        * 0.5f - 0.25f + 6.0f * offy[j];
        gx = fminf(fmaxf(gx, 0.0f), (float)(WW - 1));
        gy = fminf(fmaxf(gy, 0.0f), (float)(HH - 1));
        int x0 = (int)gx;   // floor (gx >= 0)
        int y0 = (int)gy;
        float wx = gx - (float)x0;
        float wy = gy - (float)y0;
        dx[j]  = (x0 < WW - 1) ? 1  : 0;
        dy[j]  = (y0 < HH - 1) ? WW : 0;
        i00[j] = y0 * WW + x0;
        w00[j] = (1.0f - wx) * (1.0f - wy);
        w01[j] = wx * (1.0f - wy);
        w10[j] = (1.0f - wx) * wy;
        w11[j] = wx * wy;
    }

    const float* xp = x + (b * CC + gidx * CG) * (HH * WW);
    float*       op = out + ((b * CC + gidx * CG) * HS + hs) * WS + ws0;

    #pragma unroll 4
    for (int c = 0; c < CG; ++c) {
        float v[8];
        #pragma unroll
        for (int j = 0; j < 2; ++j) {               // 8 independent LDGs
            v[4 * j + 0] = __ldg(xp + i00[j]);
            v[4 * j + 1] = __ldg(xp + i00[j] + dx[j]);
            v[4 * j + 2] = __ldg(xp + i00[j] + dy[j]);
            v[4 * j + 3] = __ldg(xp + i00[j] + dy[j] + dx[j]);
        }
        float2 r;
        r.x = v[0] * w00[0] + v[1] * w01[0] + v[2] * w10[0] + v[3] * w11[0];
        r.y = v[4] * w00[1] + v[5] * w01[1] + v[6] * w10[1] + v[7] * w11[1];
        __stcs((float2*)op, r);                     // streaming store
        xp += HH * WW;
        op += HS * WS;
    }
}

extern "C" void kernel_launch(void* const* d_in, const int* in_sizes, int n_in,
                              void* d_out, int out_size) {
    const float* x    = (const float*)d_in[0];
    const float* w    = (const float*)d_in[1];
    const float* bias = (const float*)d_in[2];
    float* out        = (float*)d_out;

    conv_offset_kernel<<<(BB * HH * WW) / 128, 256>>>(x, w, bias);
    gather_kernel<<<BB * GG * ((HS * WS / 2) / 256), 256>>>(x, out);
}